// round 17
// baseline (speedup 1.0000x reference)
#include <cuda_runtime.h>
#include <cuda_bf16.h>
#include <math.h>
#include <stdint.h>

// Problem constants
#define TT      4096
#define HH      1024
#define NH      16
#define HD      64
#define II      4096
#define VV      1024
#define NSTEPS  8
#define EPSF    1e-6f
#define THETAF  10000.0f

// Margin-recompute parameters
#define MR      512          // fixed recompute capacity (graph-static)
#define TAU     1e-5f        // fragility threshold on top-2 logit gap

// ---------------------------------------------------------------------------
// Scratch (device globals)
// ---------------------------------------------------------------------------
__device__ float g_hcur  [TT * HH];
__device__ float g_x     [TT * HH];
__device__ float g_q     [TT * HH];
__device__ float g_k     [TT * HH];
__device__ float g_v     [TT * HH];
__device__ float g_ctx   [TT * HH];
__device__ float g_hattn [TT * HH];
__device__ float g_g     [TT * II];
__device__ float g_u     [TT * II];
__device__ float g_logits[TT * VV];
__device__ float g_kcache[(size_t)TT * NH * NSTEPS * HD];
__device__ float g_vcache[(size_t)TT * NH * NSTEPS * HD];

// Margin machinery
__device__ float g_mingap[TT];
__device__ int   g_fidx[MR];
__device__ int   g_nflag;

// Split weights: 3 bf16 planes each, stored TRANSPOSED as [lev][N][K]
__device__ __nv_bfloat16 g_sWq  [3ULL * HH * HH];
__device__ __nv_bfloat16 g_sWk  [3ULL * HH * HH];
__device__ __nv_bfloat16 g_sWv  [3ULL * HH * HH];
__device__ __nv_bfloat16 g_sWo  [3ULL * HH * HH];
__device__ __nv_bfloat16 g_sWg  [3ULL * HH * II];
__device__ __nv_bfloat16 g_sWu  [3ULL * HH * II];
__device__ __nv_bfloat16 g_sWd  [3ULL * II * HH];
__device__ __nv_bfloat16 g_sWout[3ULL * HH * VV];

#define SB_HCUR   0
#define SB_X      1
#define SB_Q      2
#define SB_K      3
#define SB_V      4
#define SB_CTX    5
#define SB_HATTN  6
#define SB_G      7
#define SB_U      8
#define SB_LOGITS 9

__device__ __forceinline__ float* sel_buf(int s) {
    switch (s) {
        case SB_HCUR:  return g_hcur;
        case SB_X:     return g_x;
        case SB_Q:     return g_q;
        case SB_K:     return g_k;
        case SB_V:     return g_v;
        case SB_CTX:   return g_ctx;
        case SB_HATTN: return g_hattn;
        case SB_G:     return g_g;
        case SB_U:     return g_u;
        default:       return g_logits;
    }
}

#define SW_WQ   0
#define SW_WK   1
#define SW_WV   2
#define SW_WO   3
#define SW_WG   4
#define SW_WU   5
#define SW_WD   6
#define SW_WOUT 7

__device__ __forceinline__ __nv_bfloat16* sel_w(int s) {
    switch (s) {
        case SW_WQ: return g_sWq;
        case SW_WK: return g_sWk;
        case SW_WV: return g_sWv;
        case SW_WO: return g_sWo;
        case SW_WG: return g_sWg;
        case SW_WU: return g_sWu;
        case SW_WD: return g_sWd;
        default:    return g_sWout;
    }
}

// ---------------------------------------------------------------------------
__device__ __forceinline__ void bf16_split3(float a, __nv_bfloat16& b0,
                                            __nv_bfloat16& b1, __nv_bfloat16& b2) {
    b0 = __float2bfloat16_rn(a);
    float r = a - __bfloat162float(b0);
    b1 = __float2bfloat16_rn(r);
    float r2 = r - __bfloat162float(b1);
    b2 = __float2bfloat16_rn(r2);
}

// ---------------------------------------------------------------------------
// Weight pre-split + transpose: src fp32 [K][N] -> dst bf16 [3][N][K].
// ---------------------------------------------------------------------------
__global__ void split_weight_kernel(const float* __restrict__ src, int wsel,
                                    int K, int N) {
    __nv_bfloat16* dst = sel_w(wsel);
    const size_t PS = (size_t)K * N;
    __shared__ float ts[32][33];
    int k0 = blockIdx.x * 32, n0 = blockIdx.y * 32;
    int tx = threadIdx.x, ty = threadIdx.y;   // block (32,8)
    #pragma unroll
    for (int i = 0; i < 4; i++)
        ts[ty + i * 8][tx] = src[(size_t)(k0 + ty + i * 8) * N + n0 + tx];
    __syncthreads();
    #pragma unroll
    for (int i = 0; i < 4; i++) {
        int n = n0 + ty + i * 8;
        int k = k0 + tx;
        float a = ts[tx][ty + i * 8];
        __nv_bfloat16 b0, b1, b2;
        bf16_split3(a, b0, b1, b2);
        size_t o = (size_t)n * K + k;
        dst[o]          = b0;
        dst[PS + o]     = b1;
        dst[2 * PS + o] = b2;
    }
}

// ---------------------------------------------------------------------------
__global__ void init_flags_kernel() {
    int i = blockIdx.x * blockDim.x + threadIdx.x;
    if (i < TT) g_mingap[i] = 1e30f;
    if (i < MR) g_fidx[i] = 0;
    if (i == 0) g_nflag = 0;
}

// ---------------------------------------------------------------------------
__global__ void copy_in_kernel(const float* __restrict__ src, int n4) {
    int i = blockIdx.x * blockDim.x + threadIdx.x;
    if (i < n4) {
        reinterpret_cast<float4*>(g_hcur)[i] = reinterpret_cast<const float4*>(src)[i];
    }
}

// ---------------------------------------------------------------------------
__global__ void rmsnorm_kernel(int src_sel, const float* __restrict__ w) {
    const float* in = sel_buf(src_sel);
    int t = blockIdx.x;
    int tid = threadIdx.x;
    float4 vv = reinterpret_cast<const float4*>(in + (size_t)t * HH)[tid];
    float ss = vv.x * vv.x + vv.y * vv.y + vv.z * vv.z + vv.w * vv.w;
    #pragma unroll
    for (int o = 16; o > 0; o >>= 1) ss += __shfl_xor_sync(0xffffffffu, ss, o);
    __shared__ float warp_ss[8];
    int wid = tid >> 5, lane = tid & 31;
    if (lane == 0) warp_ss[wid] = ss;
    __syncthreads();
    if (wid == 0) {
        float s = (lane < 8) ? warp_ss[lane] : 0.0f;
        #pragma unroll
        for (int o = 4; o > 0; o >>= 1) s += __shfl_xor_sync(0xffffffffu, s, o);
        if (lane == 0) warp_ss[0] = s;
    }
    __syncthreads();
    float scale = rsqrtf(warp_ss[0] * (1.0f / HH) + EPSF);
    const float4 w4 = reinterpret_cast<const float4*>(w)[tid];
    float4 o4;
    o4.x = vv.x * scale * w4.x;
    o4.y = vv.y * scale * w4.y;
    o4.z = vv.z * scale * w4.z;
    o4.w = vv.w * scale * w4.w;
    reinterpret_cast<float4*>(g_x + (size_t)t * HH)[tid] = o4;
}

// ---------------------------------------------------------------------------
__device__ __forceinline__ void mma_bf16(float* c, const uint32_t* a, const uint32_t* b) {
    asm volatile(
        "mma.sync.aligned.m16n8k16.row.col.f32.bf16.bf16.f32 "
        "{%0,%1,%2,%3}, {%4,%5,%6,%7}, {%8,%9}, {%0,%1,%2,%3};"
        : "+f"(c[0]), "+f"(c[1]), "+f"(c[2]), "+f"(c[3])
        : "r"(a[0]), "r"(a[1]), "r"(a[2]), "r"(a[3]), "r"(b[0]), "r"(b[1]));
}

// ---------------------------------------------------------------------------
// PASS-1 GEMM: bf16 tensor cores, 8-product exact split (~1e-6 error class).
// C[M,N] = A[M,K](fp32) * W (+resid) (+bias), W pre-split bf16 [3][N][K].
// ---------------------------------------------------------------------------
#define HROW 24

template <int RESID, int BIAS>
__global__ __launch_bounds__(256)
void bmma_gemm_kernel(int asel, int wsel, int csel, int rsel,
                      const float* __restrict__ bias, int M, int N, int K) {
    const float* A  = sel_buf(asel);
    const __nv_bfloat16* Wp = sel_w(wsel);
    float*       C  = sel_buf(csel);
    const float* Rp = RESID ? sel_buf(rsel) : (const float*)0;
    const size_t PS = (size_t)K * N;

    __shared__ __align__(16) uint16_t As[3][128][HROW];
    __shared__ __align__(16) uint16_t Bs[3][128][HROW];

    const int bx = blockIdx.x, by = blockIdx.y;
    const int tid = threadIdx.x;
    const int wid = tid >> 5, lane = tid & 31;
    const int warp_m = wid >> 2;
    const int warp_n = wid & 3;
    const int gid = lane >> 2;
    const int tig = lane & 3;

    float acc[4][4][4];
    #pragma unroll
    for (int mt = 0; mt < 4; mt++)
        #pragma unroll
        for (int nt = 0; nt < 4; nt++)
            #pragma unroll
            for (int r = 0; r < 4; r++) acc[mt][nt][r] = 0.0f;

    float4 pa0, pa1;
    uint4  pbv[3];
    const int arow = tid >> 1;
    const int akq  = (tid & 1) * 8;
    const int bn   = tid >> 1;
    const int bh   = (tid & 1) * 8;

    #define GLOAD(k0)                                                          \
        {                                                                      \
            const float* ap = A + (size_t)(by * 128 + arow) * K + (k0) + akq;  \
            pa0 = *reinterpret_cast<const float4*>(ap);                        \
            pa1 = *reinterpret_cast<const float4*>(ap + 4);                    \
            size_t bo = (size_t)(bx * 128 + bn) * K + (k0) + bh;               \
            pbv[0] = *reinterpret_cast<const uint4*>(Wp + bo);                 \
            pbv[1] = *reinterpret_cast<const uint4*>(Wp + PS + bo);            \
            pbv[2] = *reinterpret_cast<const uint4*>(Wp + 2 * PS + bo);        \
        }

    #define SSTORE()                                                           \
        {                                                                      \
            float av[8] = {pa0.x, pa0.y, pa0.z, pa0.w,                         \
                           pa1.x, pa1.y, pa1.z, pa1.w};                        \
            uint16_t h0[8], h1[8], h2[8];                                      \
            _Pragma("unroll")                                                  \
            for (int e = 0; e < 8; e++) {                                      \
                __nv_bfloat16 b0, b1, b2;                                      \
                bf16_split3(av[e], b0, b1, b2);                                \
                h0[e] = __bfloat16_as_ushort(b0);                              \
                h1[e] = __bfloat16_as_ushort(b1);                              \
                h2[e] = __bfloat16_as_ushort(b2);                              \
            }                                                                  \
            *reinterpret_cast<uint4*>(&As[0][arow][akq]) =                     \
                *reinterpret_cast<uint4*>(h0);                                 \
            *reinterpret_cast<uint4*>(&As[1][arow][akq]) =                     \
                *reinterpret_cast<uint4*>(h1);                                 \
            *reinterpret_cast<uint4*>(&As[2][arow][akq]) =                     \
                *reinterpret_cast<uint4*>(h2);                                 \
            *reinterpret_cast<uint4*>(&Bs[0][bn][bh]) = pbv[0];                \
            *reinterpret_cast<uint4*>(&Bs[1][bn][bh]) = pbv[1];                \
            *reinterpret_cast<uint4*>(&Bs[2][bn][bh]) = pbv[2];                \
        }

    GLOAD(0);
    const int NK = K / 16;
    for (int kt = 0; kt < NK; kt++) {
        __syncthreads();
        SSTORE();
        __syncthreads();
        if (kt + 1 < NK) GLOAD((kt + 1) * 16);

        uint32_t bfr[3][4][2];
        #pragma unroll
        for (int lev = 0; lev < 3; lev++)
            #pragma unroll
            for (int nt = 0; nt < 4; nt++) {
                const uint32_t* wp =
                    reinterpret_cast<const uint32_t*>(&Bs[lev][warp_n * 32 + nt * 8 + gid][0]);
                bfr[lev][nt][0] = wp[tig];
                bfr[lev][nt][1] = wp[tig + 4];
            }

        #pragma unroll
        for (int mt = 0; mt < 4; mt++) {
            int r0 = warp_m * 64 + mt * 16 + gid;
            uint32_t af[3][4];
            #pragma unroll
            for (int lev = 0; lev < 3; lev++) {
                const uint32_t* w0 = reinterpret_cast<const uint32_t*>(&As[lev][r0][0]);
                const uint32_t* w1 = reinterpret_cast<const uint32_t*>(&As[lev][r0 + 8][0]);
                af[lev][0] = w0[tig];
                af[lev][1] = w1[tig];
                af[lev][2] = w0[tig + 4];
                af[lev][3] = w1[tig + 4];
            }
            #pragma unroll
            for (int nt = 0; nt < 4; nt++) {
                float* c = acc[mt][nt];
                mma_bf16(c, af[0], bfr[0][nt]);
                mma_bf16(c, af[0], bfr[1][nt]);
                mma_bf16(c, af[1], bfr[0][nt]);
                mma_bf16(c, af[1], bfr[1][nt]);
                mma_bf16(c, af[0], bfr[2][nt]);
                mma_bf16(c, af[2], bfr[0][nt]);
                mma_bf16(c, af[1], bfr[2][nt]);
                mma_bf16(c, af[2], bfr[1][nt]);
            }
        }
    }

    #pragma unroll
    for (int mt = 0; mt < 4; mt++) {
        #pragma unroll
        for (int nt = 0; nt < 4; nt++) {
            int row0 = by * 128 + warp_m * 64 + mt * 16 + gid;
            int col0 = bx * 128 + warp_n * 32 + nt * 8 + tig * 2;
            size_t i0 = (size_t)row0 * N + col0;
            size_t i1 = (size_t)(row0 + 8) * N + col0;
            float2 r0, r1;
            r0.x = acc[mt][nt][0]; r0.y = acc[mt][nt][1];
            r1.x = acc[mt][nt][2]; r1.y = acc[mt][nt][3];
            if (RESID) {
                float2 q0 = *reinterpret_cast<const float2*>(Rp + i0);
                float2 q1 = *reinterpret_cast<const float2*>(Rp + i1);
                r0.x += q0.x; r0.y += q0.y;
                r1.x += q1.x; r1.y += q1.y;
            }
            if (BIAS) {
                float2 bb = *reinterpret_cast<const float2*>(bias + col0);
                r0.x += bb.x; r0.y += bb.y;
                r1.x += bb.x; r1.y += bb.y;
            }
            *reinterpret_cast<float2*>(C + i0) = r0;
            *reinterpret_cast<float2*>(C + i1) = r1;
        }
    }
}

// ---------------------------------------------------------------------------
// PASS-2 GEMM: fp32 FFMA, BK=8 -- bit-identical to the R13 rel_err=0.0 kernel.
// ---------------------------------------------------------------------------
template <int RESID, int BIAS>
__global__ __launch_bounds__(256, 2)
void sgemm_kernel(int asel, const float* __restrict__ B, int csel, int rsel,
                  const float* __restrict__ bias, int M, int N, int K) {
    const float* A  = sel_buf(asel);
    float*       C  = sel_buf(csel);
    const float* Rp = RESID ? sel_buf(rsel) : (const float*)0;

    __shared__ float As2[8][132];
    __shared__ float Bs2[8][128];

    const int bx = blockIdx.x, by = blockIdx.y;
    const int tid = threadIdx.x;
    const int tx = tid & 15;
    const int ty = tid >> 4;

    float acc[8][8];
    #pragma unroll
    for (int i = 0; i < 8; i++)
        #pragma unroll
        for (int j = 0; j < 8; j++) acc[i][j] = 0.0f;

    const int arow = tid >> 1;
    const int acol = (tid & 1) * 4;
    const int brow = tid >> 5;
    const int bcol = (tid & 31) * 4;

    const float* Aptr = A + (size_t)(by * 128 + arow) * K + acol;
    const float* Bptr = B + (size_t)brow * N + bx * 128 + bcol;

    for (int k0 = 0; k0 < K; k0 += 8) {
        float4 a4 = *reinterpret_cast<const float4*>(Aptr + k0);
        float4 b4 = *reinterpret_cast<const float4*>(Bptr + (size_t)k0 * N);
        As2[acol + 0][arow] = a4.x;
        As2[acol + 1][arow] = a4.y;
        As2[acol + 2][arow] = a4.z;
        As2[acol + 3][arow] = a4.w;
        *reinterpret_cast<float4*>(&Bs2[brow][bcol]) = b4;
        __syncthreads();
        #pragma unroll
        for (int kk = 0; kk < 8; kk++) {
            float4 a0 = *reinterpret_cast<const float4*>(&As2[kk][ty * 8]);
            float4 a1 = *reinterpret_cast<const float4*>(&As2[kk][ty * 8 + 4]);
            float4 b0 = *reinterpret_cast<const float4*>(&Bs2[kk][tx * 8]);
            float4 b1 = *reinterpret_cast<const float4*>(&Bs2[kk][tx * 8 + 4]);
            float ar[8] = {a0.x, a0.y, a0.z, a0.w, a1.x, a1.y, a1.z, a1.w};
            float br[8] = {b0.x, b0.y, b0.z, b0.w, b1.x, b1.y, b1.z, b1.w};
            #pragma unroll
            for (int i = 0; i < 8; i++)
                #pragma unroll
                for (int j = 0; j < 8; j++)
                    acc[i][j] = fmaf(ar[i], br[j], acc[i][j]);
        }
        __syncthreads();
    }

    #pragma unroll
    for (int i = 0; i < 8; i++) {
        int row = by * 128 + ty * 8 + i;
        #pragma unroll
        for (int j = 0; j < 8; j += 4) {
            int col = bx * 128 + tx * 8 + j;
            size_t idx = (size_t)row * N + col;
            float4 r;
            r.x = acc[i][j + 0]; r.y = acc[i][j + 1];
            r.z = acc[i][j + 2]; r.w = acc[i][j + 3];
            if (RESID) {
                float4 rr = *reinterpret_cast<const float4*>(Rp + idx);
                r.x += rr.x; r.y += rr.y; r.z += rr.z; r.w += rr.w;
            }
            if (BIAS) {
                float4 bb = *reinterpret_cast<const float4*>(bias + col);
                r.x += bb.x; r.y += bb.y; r.z += bb.z; r.w += bb.w;
            }
            *reinterpret_cast<float4*>(C + idx) = r;
        }
    }
}

// ---------------------------------------------------------------------------
__global__ void qkv_post_kernel(int p) {
    int t = blockIdx.x;
    int head = threadIdx.x >> 5;
    int i = threadIdx.x & 31;
    size_t base = (size_t)t * HH + head * HD;
    float invf = 1.0f / powf(THETAF, (2.0f * (float)i) / (float)HD);
    float ang = (float)p * invf;
    float c = cosf(ang), s = sinf(ang);

    float x1 = g_q[base + i], x2 = g_q[base + i + 32];
    g_q[base + i]      = x1 * c - x2 * s;
    g_q[base + i + 32] = x2 * c + x1 * s;

    size_t cb = (((size_t)t * NH + head) * NSTEPS + p) * HD;
    x1 = g_k[base + i]; x2 = g_k[base + i + 32];
    g_kcache[cb + i]      = x1 * c - x2 * s;
    g_kcache[cb + i + 32] = x2 * c + x1 * s;

    g_vcache[cb + i]      = g_v[base + i];
    g_vcache[cb + i + 32] = g_v[base + i + 32];
}

// ---------------------------------------------------------------------------
__global__ void attn_kernel(int p) {
    int gw = (blockIdx.x * blockDim.x + threadIdx.x) >> 5;
    int lane = threadIdx.x & 31;
    int t = gw / NH, head = gw % NH;

    float2 q2 = *reinterpret_cast<const float2*>(g_q + (size_t)t * HH + head * HD + lane * 2);
    size_t cbase = ((size_t)t * NH + head) * NSTEPS * HD;

    float sc[NSTEPS];
    float mx = -1e30f;
    for (int m = 0; m <= p; m++) {
        float2 k2 = *reinterpret_cast<const float2*>(g_kcache + cbase + m * HD + lane * 2);
        float d = q2.x * k2.x + q2.y * k2.y;
        #pragma unroll
        for (int o = 16; o > 0; o >>= 1) d += __shfl_xor_sync(0xffffffffu, d, o);
        d *= 0.125f;
        sc[m] = d;
        mx = fmaxf(mx, d);
    }
    float sum = 0.0f;
    for (int m = 0; m <= p; m++) { sc[m] = expf(sc[m] - mx); sum += sc[m]; }
    float inv = 1.0f / sum;
    float cx = 0.0f, cy = 0.0f;
    for (int m = 0; m <= p; m++) {
        float2 v2 = *reinterpret_cast<const float2*>(g_vcache + cbase + m * HD + lane * 2);
        float w = sc[m] * inv;
        cx = fmaf(w, v2.x, cx);
        cy = fmaf(w, v2.y, cy);
    }
    float2 o2; o2.x = cx; o2.y = cy;
    *reinterpret_cast<float2*>(g_ctx + (size_t)t * HH + head * HD + lane * 2) = o2;
}

// ---------------------------------------------------------------------------
__global__ void silu_mul_kernel(int n) {
    int i = blockIdx.x * blockDim.x + threadIdx.x;
    if (i < n) {
        float gv = g_g[i];
        float sv = gv / (1.0f + expf(-gv));
        g_g[i] = sv * g_u[i];
    }
}

// ---------------------------------------------------------------------------
// PASS-1 argmax: token (float32) + top-2 gap tracking + E-gather.
// ---------------------------------------------------------------------------
__global__ void argmax_gap_kernel(const float* __restrict__ E,
                                  float* __restrict__ out, int p) {
    int t = blockIdx.x;
    int tid = threadIdx.x;
    const float* row = g_logits + (size_t)t * VV;
    float v1 = -3.402823466e+38f, v2 = -3.402823466e+38f;
    int i1 = 0;
    for (int j = tid; j < VV; j += 256) {
        float v = row[j];
        if (!isfinite(v)) continue;
        if (v > v1 || (v == v1 && j < i1)) { v2 = v1; v1 = v; i1 = j; }
        else if (v > v2) v2 = v;
    }
    __shared__ float sv1[256], sv2[256];
    __shared__ int   si1[256];
    sv1[tid] = v1; si1[tid] = i1; sv2[tid] = v2;
    __syncthreads();
    for (int s = 128; s > 0; s >>= 1) {
        if (tid < s) {
            float av1 = sv1[tid],     bv1 = sv1[tid + s];
            int   ai1 = si1[tid],     bi1 = si1[tid + s];
            float av2 = sv2[tid],     bv2 = sv2[tid + s];
            if (bv1 > av1 || (bv1 == av1 && bi1 < ai1)) {
                sv1[tid] = bv1; si1[tid] = bi1;
                sv2[tid] = fmaxf(bv2, av1);
            } else {
                sv2[tid] = fmaxf(av2, bv1);
            }
        }
        __syncthreads();
    }
    int tok = si1[0];
    tok = (tok < 0) ? 0 : ((tok >= VV) ? (VV - 1) : tok);
    if (tid == 0) {
        out[(size_t)t * NSTEPS + p] = (float)tok;
        float gap = sv1[0] - sv2[0];
        if (!isfinite(gap)) gap = 0.0f;
        g_mingap[t] = fminf(g_mingap[t], gap);
    }
    const float4* erow = reinterpret_cast<const float4*>(E + (size_t)tok * HH);
    reinterpret_cast<float4*>(g_hcur + (size_t)t * HH)[tid] = erow[tid];
}

// ---------------------------------------------------------------------------
__global__ void compact_kernel() {
    int t = blockIdx.x * blockDim.x + threadIdx.x;
    if (t < TT && g_mingap[t] < TAU) {
        int pos = atomicAdd(&g_nflag, 1);
        if (pos < MR) g_fidx[pos] = t;
    }
}

// ---------------------------------------------------------------------------
__global__ void gather_rows_kernel(const float* __restrict__ src) {
    int s = blockIdx.x;                    // grid = MR
    int t = g_fidx[s];
    float4 v = reinterpret_cast<const float4*>(src + (size_t)t * HH)[threadIdx.x];
    reinterpret_cast<float4*>(g_hcur + (size_t)s * HH)[threadIdx.x] = v;
}

// ---------------------------------------------------------------------------
// PASS-2 argmax: bit-identical selection to R13, scatter via g_fidx.
// ---------------------------------------------------------------------------
__global__ void argmax_scatter_kernel(const float* __restrict__ E,
                                      float* __restrict__ out, int p) {
    int s = blockIdx.x;                    // grid = MR
    int tid = threadIdx.x;
    const float* row = g_logits + (size_t)s * VV;
    float bv = -3.402823466e+38f;
    int bi = 0;
    for (int j = tid; j < VV; j += 256) {
        float vv = row[j];
        if (!isfinite(vv)) continue;
        if (vv > bv || (vv == bv && j < bi)) { bv = vv; bi = j; }
    }
    __shared__ float sv[256];
    __shared__ int   si[256];
    sv[tid] = bv; si[tid] = bi;
    __syncthreads();
    for (int st = 128; st > 0; st >>= 1) {
        if (tid < st) {
            if (sv[tid + st] > sv[tid] ||
                (sv[tid + st] == sv[tid] && si[tid + st] < si[tid])) {
                sv[tid] = sv[tid + st]; si[tid] = si[tid + st];
            }
        }
        __syncthreads();
    }
    int tok = si[0];
    tok = (tok < 0) ? 0 : ((tok >= VV) ? (VV - 1) : tok);
    if (tid == 0) out[(size_t)g_fidx[s] * NSTEPS + p] = (float)tok;
    const float4* erow = reinterpret_cast<const float4*>(E + (size_t)tok * HH);
    reinterpret_cast<float4*>(g_hcur + (size_t)s * HH)[tid] = erow[tid];
}

// ---------------------------------------------------------------------------
// Host driver (dict input order; float32 token output -- both proven).
// ---------------------------------------------------------------------------
static void launch_bmma(int asel, int wsel, int csel, int rsel,
                        const float* bias, int M, int N, int K) {
    dim3 grid(N / 128, M / 128), block(256);
    if (rsel >= 0)   bmma_gemm_kernel<1, 0><<<grid, block>>>(asel, wsel, csel, rsel, (const float*)0, M, N, K);
    else if (bias)   bmma_gemm_kernel<0, 1><<<grid, block>>>(asel, wsel, csel, 0, bias, M, N, K);
    else             bmma_gemm_kernel<0, 0><<<grid, block>>>(asel, wsel, csel, 0, (const float*)0, M, N, K);
}

static void launch_sgemm(int asel, const float* B, int csel, int rsel,
                         const float* bias, int M, int N, int K) {
    dim3 grid(N / 128, M / 128), block(256);
    if (rsel >= 0)   sgemm_kernel<1, 0><<<grid, block>>>(asel, B, csel, rsel, (const float*)0, M, N, K);
    else if (bias)   sgemm_kernel<0, 1><<<grid, block>>>(asel, B, csel, 0, bias, M, N, K);
    else             sgemm_kernel<0, 0><<<grid, block>>>(asel, B, csel, 0, (const float*)0, M, N, K);
}

extern "C" void kernel_launch(void* const* d_in, const int* in_sizes, int n_in,
                              void* d_out, int out_size) {
    const float* in_h = (const float*)d_in[0];
    const float* Wq   = (const float*)d_in[1];
    const float* Wk   = (const float*)d_in[2];
    const float* Wv   = (const float*)d_in[3];
    const float* Wo   = (const float*)d_in[4];
    const float* Wg   = (const float*)d_in[5];
    const float* Wu   = (const float*)d_in[6];
    const float* Wd   = (const float*)d_in[7];
    const float* n1   = (const float*)d_in[8];
    const float* n2   = (const float*)d_in[9];
    const float* E    = (const float*)d_in[10];
    const float* Wout = (const float*)d_in[11];
    const float* bout = (const float*)d_in[12];
    float* out = (float*)d_out;

    init_flags_kernel<<<(TT + 255) / 256, 256>>>();

    {
        dim3 blk(32, 8);
        split_weight_kernel<<<dim3(HH / 32, HH / 32), blk>>>(Wq,   SW_WQ,   HH, HH);
        split_weight_kernel<<<dim3(HH / 32, HH / 32), blk>>>(Wk,   SW_WK,   HH, HH);
        split_weight_kernel<<<dim3(HH / 32, HH / 32), blk>>>(Wv,   SW_WV,   HH, HH);
        split_weight_kernel<<<dim3(HH / 32, HH / 32), blk>>>(Wo,   SW_WO,   HH, HH);
        split_weight_kernel<<<dim3(HH / 32, II / 32), blk>>>(Wg,   SW_WG,   HH, II);
        split_weight_kernel<<<dim3(HH / 32, II / 32), blk>>>(Wu,   SW_WU,   HH, II);
        split_weight_kernel<<<dim3(II / 32, HH / 32), blk>>>(Wd,   SW_WD,   II, HH);
        split_weight_kernel<<<dim3(HH / 32, VV / 32), blk>>>(Wout, SW_WOUT, HH, VV);
    }

    // ---------------- PASS 1: full batch, tensor-core GEMMs ----------------
    {
        int n4 = TT * HH / 4;
        copy_in_kernel<<<(n4 + 255) / 256, 256>>>(in_h, n4);
    }
    for (int p = 0; p < NSTEPS; p++) {
        rmsnorm_kernel<<<TT, 256>>>(SB_HCUR, n1);
        launch_bmma(SB_X, SW_WQ, SB_Q, -1, (const float*)0, TT, HH, HH);
        launch_bmma(SB_X, SW_WK, SB_K, -1, (const float*)0, TT, HH, HH);
        launch_bmma(SB_X, SW_WV, SB_V, -1, (const float*)0, TT, HH, HH);
        qkv_post_kernel<<<TT, NH * 32>>>(p);
        attn_kernel<<<TT * NH / 8, 256>>>(p);
        launch_bmma(SB_CTX, SW_WO, SB_HATTN, SB_HCUR, (const float*)0, TT, HH, HH);
        rmsnorm_kernel<<<TT, 256>>>(SB_HATTN, n2);
        launch_bmma(SB_X, SW_WG, SB_G, -1, (const float*)0, TT, II, HH);
        launch_bmma(SB_X, SW_WU, SB_U, -1, (const float*)0, TT, II, HH);
        silu_mul_kernel<<<(TT * II + 255) / 256, 256>>>(TT * II);
        launch_bmma(SB_G, SW_WD, SB_HCUR, SB_HATTN, (const float*)0, TT, HH, II);
        launch_bmma(SB_HCUR, SW_WOUT, SB_LOGITS, -1, bout, TT, VV, HH);
        argmax_gap_kernel<<<TT, 256>>>(E, out, p);
    }

    // ---------------- PASS 2: fragile rows, exact fp32 (R13) ---------------
    compact_kernel<<<(TT + 255) / 256, 256>>>();
    gather_rows_kernel<<<MR, 256>>>(in_h);
    for (int p = 0; p < NSTEPS; p++) {
        rmsnorm_kernel<<<MR, 256>>>(SB_HCUR, n1);
        launch_sgemm(SB_X, Wq, SB_Q, -1, (const float*)0, MR, HH, HH);
        launch_sgemm(SB_X, Wk, SB_K, -1, (const float*)0, MR, HH, HH);
        launch_sgemm(SB_X, Wv, SB_V, -1, (const float*)0, MR, HH, HH);
        qkv_post_kernel<<<MR, NH * 32>>>(p);
        attn_kernel<<<MR * NH / 8, 256>>>(p);
        launch_sgemm(SB_CTX, Wo, SB_HATTN, SB_HCUR, (const float*)0, MR, HH, HH);
        rmsnorm_kernel<<<MR, 256>>>(SB_HATTN, n2);
        launch_sgemm(SB_X, Wg, SB_G, -1, (const float*)0, MR, II, HH);
        launch_sgemm(SB_X, Wu, SB_U, -1, (const float*)0, MR, II, HH);
        silu_mul_kernel<<<(MR * II + 255) / 256, 256>>>(MR * II);
        launch_sgemm(SB_G, Wd, SB_HCUR, SB_HATTN, (const float*)0, MR, HH, II);
        launch_sgemm(SB_HCUR, Wout, SB_LOGITS, -1, bout, MR, VV, HH);
        argmax_scatter_kernel<<<MR, 256>>>(E, out, p);
    }
}